// round 14
// baseline (speedup 1.0000x reference)
#include <cuda_runtime.h>
#include <cuda_bf16.h>
#include <cstdint>

#define NN 4096
#define DD 128
#define HH 8
#define ALPHA 0.2f
#define EPSLN 1e-5f

// ---------------- scratch ----------------
__device__ __nv_bfloat16 g_Whb[HH * NN * DD];    // [h][m][e] bf16 (attn values)
__device__ __nv_bfloat16 g_nodesb[NN * DD];      // nodes bf16
__device__ __nv_bfloat16 g_Wb[HH * DD * DD];     // W bf16 [h][d][e]
__device__ __nv_bfloat16 g_W1b[HH * DD * DD];    // W1 bf16 [1024][128]
__device__ __nv_bfloat16 g_attnb[NN * HH * DD];  // cat = elu(attn) bf16 [n][h*128+e]
__device__ float2 g_eq1[HH * NN];                // (e^{f1}, e^{0.2 f1})
__device__ float2 g_eq2[HH * NN];                // (e^{f2}, e^{0.2 f2})
__device__ unsigned g_adjbits[NN * (NN / 32)];   // 2MB bitmask

// ---------------- helpers ----------------
__device__ __forceinline__ uint32_t smem_u32(const void* p) {
    uint32_t a;
    asm("{ .reg .u64 t; cvta.to.shared.u64 t, %1; cvt.u32.u64 %0, t; }" : "=r"(a) : "l"(p));
    return a;
}
__device__ __forceinline__ void cp_async16(uint32_t sdst, const void* gsrc) {
    asm volatile("cp.async.cg.shared.global [%0], [%1], 16;" :: "r"(sdst), "l"(gsrc) : "memory");
}
__device__ __forceinline__ void cp_commit() {
    asm volatile("cp.async.commit_group;" ::: "memory");
}
__device__ __forceinline__ void cp_wait0() {
    asm volatile("cp.async.wait_group 0;" ::: "memory");
}
__device__ __forceinline__ void cp_wait1() {
    asm volatile("cp.async.wait_group 1;" ::: "memory");
}
__device__ __forceinline__ void ldmatrix_x4(uint32_t& b0, uint32_t& b1, uint32_t& b2,
                                            uint32_t& b3, uint32_t addr) {
    asm volatile("ldmatrix.sync.aligned.m8n8.x4.shared.b16 {%0,%1,%2,%3}, [%4];"
                 : "=r"(b0), "=r"(b1), "=r"(b2), "=r"(b3) : "r"(addr));
}
__device__ __forceinline__ void ldmatrix_x4_trans(uint32_t& b0, uint32_t& b1, uint32_t& b2,
                                                  uint32_t& b3, uint32_t addr) {
    asm volatile("ldmatrix.sync.aligned.m8n8.x4.trans.shared.b16 {%0,%1,%2,%3}, [%4];"
                 : "=r"(b0), "=r"(b1), "=r"(b2), "=r"(b3) : "r"(addr));
}
__device__ __forceinline__ void mma16816(float* c, uint32_t a0, uint32_t a1, uint32_t a2,
                                         uint32_t a3, uint32_t b0, uint32_t b1) {
    asm volatile(
        "mma.sync.aligned.m16n8k16.row.col.f32.bf16.bf16.f32 "
        "{%0,%1,%2,%3}, {%4,%5,%6,%7}, {%8,%9}, {%0,%1,%2,%3};"
        : "+f"(c[0]), "+f"(c[1]), "+f"(c[2]), "+f"(c[3])
        : "r"(a0), "r"(a1), "r"(a2), "r"(a3), "r"(b0), "r"(b1));
}
// swizzled 16B-chunk index: 256B rows (16 chunks) and 128B rows (8 chunks)
__device__ __forceinline__ uint32_t swz(uint32_t j, uint32_t row) {
    return (j & 8u) | ((j ^ row) & 7u);
}
__device__ __forceinline__ uint32_t swz8(uint32_t j, uint32_t row) {
    return (j ^ row) & 7u;
}
__device__ __forceinline__ float eluf(float v) { return v > 0.f ? v : expm1f(v); }

// ============================================================
// K_pre: fused front-end. Blocks [0,4096): adj bits; [4096,4352): bf16 casts.
// ============================================================
__global__ void __launch_bounds__(256) k_pre(const float* __restrict__ nodes,
                                             const float* __restrict__ W,
                                             const float* __restrict__ W1,
                                             const int* __restrict__ adj) {
    int b = blockIdx.x;
    if (b < NN) {
        int n = b;
        int wid = threadIdx.x >> 5, lane = threadIdx.x & 31;
        for (int j = wid; j < NN / 32; j += 8) {
            int v = adj[(long long)n * NN + j * 32 + lane];
            unsigned bal = __ballot_sync(0xffffffffu, v > 0);
            if (lane == 0) g_adjbits[n * (NN / 32) + j] = bal;
        }
    } else {
        int cb = b - NN;                      // 0..255
        int idx = cb * 256 + threadIdx.x;
        for (int i = idx; i < (NN * DD) / 2; i += 256 * 256) {
            float2 v = *(const float2*)&nodes[i * 2];
            __nv_bfloat162 bb = __floats2bfloat162_rn(v.x, v.y);
            *(uint32_t*)&g_nodesb[i * 2] = *(uint32_t*)&bb;
        }
        for (int i = idx; i < (HH * DD * DD) / 2; i += 256 * 256) {
            float2 v = *(const float2*)&W[i * 2];
            __nv_bfloat162 bb = __floats2bfloat162_rn(v.x, v.y);
            *(uint32_t*)&g_Wb[i * 2] = *(uint32_t*)&bb;
            float2 v1 = *(const float2*)&W1[i * 2];
            __nv_bfloat162 b1v = __floats2bfloat162_rn(v1.x, v1.y);
            *(uint32_t*)&g_W1b[i * 2] = *(uint32_t*)&b1v;
        }
    }
}

// ============================================================
// K_wh_mma: Wh[h] = nodes @ W[h] on tensor cores -> bf16 [h][m][e].
// Epilogue also computes f1 = Wh·a1, f2 = Wh·a2 from the fp32 accumulators
// (quad shfl-reduce) and writes (e^f, e^{0.2f}) pairs.
// ============================================================
#define WH_SMEM (65536 + 1024)
__global__ void __launch_bounds__(256, 2) k_wh_mma(const float* __restrict__ a1,
                                                   const float* __restrict__ a2) {
    extern __shared__ char smem[];
    uint32_t sbase = smem_u32(smem);
    uint32_t abase = sbase;
    uint32_t wbase = sbase + 32768;
    float* a1s = (float*)(smem + 65536);
    float* a2s = (float*)(smem + 65536 + 512);
    int h = blockIdx.y;
    int n0 = blockIdx.x * 128;
    int t = threadIdx.x;
    int lane = t & 31, w = t >> 5;

#pragma unroll
    for (int i = 0; i < 8; ++i) {
        int u = t + i * 256;  // 0..2047
        uint32_t row = u >> 4, j = u & 15;
        cp_async16(abase + row * 256 + (swz(j, row) << 4),
                   g_nodesb + (long long)(n0 + row) * DD + j * 8);
        cp_async16(wbase + row * 256 + (swz(j, row) << 4),
                   g_Wb + (long long)h * DD * DD + row * DD + j * 8);
    }
    if (t < 128) {
        a1s[t] = a1[h * DD + t];
        a2s[t] = a2[h * DD + t];
    }
    cp_commit();
    cp_wait0();
    __syncthreads();

    int qr = lane >> 2, ko = (lane & 3) * 2;
    int lr16 = lane & 15, hi = lane >> 4;
    float c[16][4];
#pragma unroll
    for (int j = 0; j < 16; ++j) c[j][0] = c[j][1] = c[j][2] = c[j][3] = 0.f;

#pragma unroll
    for (int k = 0; k < 8; ++k) {
        uint32_t arow = (uint32_t)(w * 16 + lr16);
        uint32_t aj = (uint32_t)(k * 2 + hi);
        uint32_t a0, a1r, a2r, a3;
        ldmatrix_x4(a0, a1r, a2r, a3, abase + arow * 256 + (swz(aj, arow) << 4));
        uint32_t lrow = (uint32_t)(k * 16 + lr16);
        uint32_t rowb = wbase + lrow * 256;
#pragma unroll
        for (int jj = 0; jj < 8; ++jj) {
            uint32_t j2 = (uint32_t)(jj * 2 + hi);
            uint32_t v0, v1, v2, v3;
            ldmatrix_x4_trans(v0, v1, v2, v3, rowb + (swz(j2, lrow) << 4));
            mma16816(c[jj * 2], a0, a1r, a2r, a3, v0, v1);
            mma16816(c[jj * 2 + 1], a0, a1r, a2r, a3, v2, v3);
        }
    }

    int gn0 = n0 + w * 16 + qr;
    __nv_bfloat16* o0 = &g_Whb[((long long)h * NN + gn0) * DD];
    __nv_bfloat16* o1 = &g_Whb[((long long)h * NN + gn0 + 8) * DD];
#pragma unroll
    for (int j = 0; j < 16; ++j) {
        __nv_bfloat162 v0 = __floats2bfloat162_rn(c[j][0], c[j][1]);
        __nv_bfloat162 v1 = __floats2bfloat162_rn(c[j][2], c[j][3]);
        *(uint32_t*)&o0[j * 8 + ko] = *(uint32_t*)&v0;
        *(uint32_t*)&o1[j * 8 + ko] = *(uint32_t*)&v1;
    }

    // ---- f epilogue: f = Wh·a (rows gn0, gn0+8) ----
    float f1a = 0.f, f1b = 0.f, f2a = 0.f, f2b = 0.f;
#pragma unroll
    for (int j = 0; j < 16; ++j) {
        float a1lo = a1s[j * 8 + ko], a1hi = a1s[j * 8 + ko + 1];
        float a2lo = a2s[j * 8 + ko], a2hi = a2s[j * 8 + ko + 1];
        f1a += c[j][0] * a1lo + c[j][1] * a1hi;
        f1b += c[j][2] * a1lo + c[j][3] * a1hi;
        f2a += c[j][0] * a2lo + c[j][1] * a2hi;
        f2b += c[j][2] * a2lo + c[j][3] * a2hi;
    }
#pragma unroll
    for (int o = 1; o <= 2; o <<= 1) {
        f1a += __shfl_xor_sync(0xffffffffu, f1a, o);
        f1b += __shfl_xor_sync(0xffffffffu, f1b, o);
        f2a += __shfl_xor_sync(0xffffffffu, f2a, o);
        f2b += __shfl_xor_sync(0xffffffffu, f2b, o);
    }
    if ((lane & 3) == 0) {
        g_eq1[h * NN + gn0] = make_float2(__expf(f1a), __expf(ALPHA * f1a));
        g_eq2[h * NN + gn0] = make_float2(__expf(f2a), __expf(ALPHA * f2a));
        g_eq1[h * NN + gn0 + 8] = make_float2(__expf(f1b), __expf(ALPHA * f1b));
        g_eq2[h * NN + gn0 + 8] = make_float2(__expf(f2b), __expf(ALPHA * f2b));
    }
}

// ============================================================
// K_attn: softmax-agg via mma.sync bf16 (R12-proven: KC=128, ones-MMA rowsum).
// p = bit ? max(e1*e2, q1*q2) : 0   (== exp(lrelu(f1+f2)), FMNMX, no branch).
// Epilogue: elu(normalized) -> bf16 cat [n][h*128+e].
// ============================================================
#define KC 128
#define BBYTES (KC * 256)         // 32KB per B buffer
#define SM_EQ2 (2 * BBYTES)       // (e2,q2)[4096] at 64KB
#define ATTN_SMEM (SM_EQ2 + NN * 8)

__global__ void __launch_bounds__(256, 2) k_attn() {
    extern __shared__ char smem[];
    uint32_t sbase = smem_u32(smem);
    float* eq2s = (float*)(smem + SM_EQ2);
    int h = blockIdx.x;
    int n0 = blockIdx.y * 128;
    int t = threadIdx.x;
    int lane = t & 31, w = t >> 5;

    // ---- preload B chunk 0 (128 m-rows x 128 cols = 32KB) ----
    const __nv_bfloat16* whb = &g_Whb[(long long)h * NN * DD];
#pragma unroll
    for (int i = 0; i < 8; ++i) {
        int u = t + i * 256;  // 0..2047
        uint32_t row = u >> 4, j = u & 15;
        cp_async16(sbase + row * 256 + (swz(j, row) << 4),
                   whb + (long long)row * DD + j * 8);
    }
    cp_commit();
    // ---- stage (e2,q2) pairs into smem ----
    {
        const float4* src = (const float4*)(g_eq2 + h * NN);
        float4* dst = (float4*)eq2s;
        for (int i = t; i < NN / 2; i += 256) dst[i] = src[i];
    }

    int qr = lane >> 2;          // 0..7
    int ko = (lane & 3) * 2;     // 0,2,4,6
    int gn0 = n0 + w * 16 + qr;
    int gn1 = gn0 + 8;
    float2 eqA = g_eq1[h * NN + gn0];
    float2 eqB = g_eq1[h * NN + gn1];
    const uint4* bp0 = (const uint4*)&g_adjbits[(long long)gn0 * (NN / 32)];
    const uint4* bp1 = (const uint4*)&g_adjbits[(long long)gn1 * (NN / 32)];
    float c[16][4];
#pragma unroll
    for (int j = 0; j < 16; ++j) c[j][0] = c[j][1] = c[j][2] = c[j][3] = 0.f;
    float crs[4] = {0.f, 0.f, 0.f, 0.f};
    __nv_bfloat162 one2 = __floats2bfloat162_rn(1.f, 1.f);
    uint32_t ONES = *(uint32_t*)&one2;

    int lr16 = lane & 15;
    int hi = lane >> 4;

    for (int ch = 0; ch < NN / KC; ++ch) {
        uint32_t bcur = sbase + (ch & 1) * BBYTES;
        if (ch + 1 < NN / KC) {
            uint32_t bnext = sbase + ((ch + 1) & 1) * BBYTES;
            const __nv_bfloat16* src = whb + (long long)(ch + 1) * KC * DD;
#pragma unroll
            for (int i = 0; i < 8; ++i) {
                int u = t + i * 256;
                uint32_t row = u >> 4, j = u & 15;
                cp_async16(bnext + row * 256 + (swz(j, row) << 4),
                           src + (long long)row * DD + j * 8);
            }
        }
        cp_commit();
        cp_wait1();
        __syncthreads();

        uint4 bw0 = bp0[ch], bw1 = bp1[ch];

#pragma unroll
        for (int s = 0; s < 8; ++s) {
            int mb = ch * KC + s * 16;
            float4 mA = *(const float4*)&eq2s[2 * (mb + ko)];       // (e2,q2) m, m+1
            float4 mB = *(const float4*)&eq2s[2 * (mb + ko + 8)];   // m+8, m+9
            uint32_t w0 = (s < 2) ? bw0.x : (s < 4) ? bw0.y : (s < 6) ? bw0.z : bw0.w;
            uint32_t w1 = (s < 2) ? bw1.x : (s < 4) ? bw1.y : (s < 6) ? bw1.z : bw1.w;
            uint32_t t0 = (w0 >> ((s & 1) * 16)) >> ko;
            uint32_t t1 = (w1 >> ((s & 1) * 16)) >> ko;
            float v00 = fmaxf(eqA.x * mA.x, eqA.y * mA.y);
            float v01 = fmaxf(eqA.x * mA.z, eqA.y * mA.w);
            float v02 = fmaxf(eqA.x * mB.x, eqA.y * mB.y);
            float v03 = fmaxf(eqA.x * mB.z, eqA.y * mB.w);
            float v10 = fmaxf(eqB.x * mA.x, eqB.y * mA.y);
            float v11 = fmaxf(eqB.x * mA.z, eqB.y * mA.w);
            float v12 = fmaxf(eqB.x * mB.x, eqB.y * mB.y);
            float v13 = fmaxf(eqB.x * mB.z, eqB.y * mB.w);
            float p00 = (t0 & 1u) ? v00 : 0.f;
            float p01 = (t0 & 2u) ? v01 : 0.f;
            float p02 = (t0 & 0x100u) ? v02 : 0.f;
            float p03 = (t0 & 0x200u) ? v03 : 0.f;
            float p10 = (t1 & 1u) ? v10 : 0.f;
            float p11 = (t1 & 2u) ? v11 : 0.f;
            float p12 = (t1 & 0x100u) ? v12 : 0.f;
            float p13 = (t1 & 0x200u) ? v13 : 0.f;
            __nv_bfloat162 A0 = __floats2bfloat162_rn(p00, p01);
            __nv_bfloat162 A1 = __floats2bfloat162_rn(p10, p11);
            __nv_bfloat162 A2 = __floats2bfloat162_rn(p02, p03);
            __nv_bfloat162 A3 = __floats2bfloat162_rn(p12, p13);
            uint32_t a0 = *(uint32_t*)&A0, a1 = *(uint32_t*)&A1;
            uint32_t a2 = *(uint32_t*)&A2, a3 = *(uint32_t*)&A3;

            uint32_t lrow = (uint32_t)(s * 16 + lr16);
            uint32_t rowb = bcur + lrow * 256;
#pragma unroll
            for (int jj = 0; jj < 8; ++jj) {
                uint32_t j2 = (uint32_t)(jj * 2 + hi);
                uint32_t addr = rowb + (swz(j2, lrow) << 4);
                uint32_t v0, v1, v2, v3;
                ldmatrix_x4_trans(v0, v1, v2, v3, addr);
                mma16816(c[jj * 2], a0, a1, a2, a3, v0, v1);
                mma16816(c[jj * 2 + 1], a0, a1, a2, a3, v2, v3);
            }
            // row-sum MMA against ones
            mma16816(crs, a0, a1, a2, a3, ONES, ONES);
        }
        __syncthreads();
    }

    float inv0 = 1.f / crs[0], inv1 = 1.f / crs[2];

    // epilogue: elu(normalized) -> bf16 cat [n][h*128+e]
    __nv_bfloat16* o0 = &g_attnb[(long long)gn0 * (HH * DD) + h * DD];
    __nv_bfloat16* o1 = &g_attnb[(long long)gn1 * (HH * DD) + h * DD];
#pragma unroll
    for (int j = 0; j < 16; ++j) {
        float v0 = eluf(c[j][0] * inv0);
        float v1 = eluf(c[j][1] * inv0);
        float v2 = eluf(c[j][2] * inv1);
        float v3 = eluf(c[j][3] * inv1);
        __nv_bfloat162 b0v = __floats2bfloat162_rn(v0, v1);
        __nv_bfloat162 b1v = __floats2bfloat162_rn(v2, v3);
        *(uint32_t*)&o0[j * 8 + ko] = *(uint32_t*)&b0v;
        *(uint32_t*)&o1[j * 8 + ko] = *(uint32_t*)&b1v;
    }
}

// ============================================================
// K_final_mma: x = elu(cat @ W1 + b1); out = LN(nodes+x).
// 16-row CTAs -> grid 256 (>148 SMs, 3 CTA/SM; fixes grid starvation).
// 8 warps = 8 col-groups of 16 cols; warp = 16r x 16c, c[2][4].
// ============================================================
#define SMF_A 0                      // 2 x 2KB
#define SMF_B 4096                   // 2 x 16KB
#define SMF_X 36864                  // 16 x 132 floats
#define FIN_SMEM (36864 + 16 * 132 * 4)

__global__ void __launch_bounds__(256, 3) k_final_mma(const float* __restrict__ nodes,
                                                      const float* __restrict__ b1,
                                                      const float* __restrict__ gamma,
                                                      const float* __restrict__ beta,
                                                      float* __restrict__ out) {
    extern __shared__ char smem[];
    uint32_t sbase = smem_u32(smem);
    float* xs = (float*)(smem + SMF_X);
    int n0 = blockIdx.x * 16;
    int t = threadIdx.x;
    int lane = t & 31, w = t >> 5;
    int cg = w;  // col-group: cols [cg*16, cg*16+16)

    // prefetch chunk 0: A = cat rows n0..n0+15 k 0..63 (2KB); B = W1 rows 0..63 (16KB)
    if (t < 128) {
        uint32_t row = (uint32_t)(t >> 3), j = (uint32_t)(t & 7);
        cp_async16(sbase + SMF_A + row * 128 + (swz8(j, row) << 4),
                   g_attnb + (long long)(n0 + row) * (HH * DD) + j * 8);
    }
#pragma unroll
    for (int i = 0; i < 4; ++i) {
        int u = t + i * 256;
        uint32_t brow = (uint32_t)(u >> 4), bj = (uint32_t)(u & 15);
        cp_async16(sbase + SMF_B + brow * 256 + (swz(bj, brow) << 4),
                   g_W1b + (long long)brow * DD + bj * 8);
    }
    cp_commit();

    int qr = lane >> 2, ko = (lane & 3) * 2;
    int lr16 = lane & 15, hi = lane >> 4;
    float c[2][4];
    c[0][0] = c[0][1] = c[0][2] = c[0][3] = 0.f;
    c[1][0] = c[1][1] = c[1][2] = c[1][3] = 0.f;

    for (int ch = 0; ch < 16; ++ch) {
        uint32_t abuf = sbase + SMF_A + (ch & 1) * 2048;
        uint32_t bbuf = sbase + SMF_B + (ch & 1) * 16384;
        if (ch + 1 < 16) {
            uint32_t abn = sbase + SMF_A + ((ch + 1) & 1) * 2048;
            uint32_t bbn = sbase + SMF_B + ((ch + 1) & 1) * 16384;
            int k0 = (ch + 1) * 64;
            if (t < 128) {
                uint32_t row = (uint32_t)(t >> 3), j = (uint32_t)(t & 7);
                cp_async16(abn + row * 128 + (swz8(j, row) << 4),
                           g_attnb + (long long)(n0 + row) * (HH * DD) + k0 + j * 8);
            }
#pragma unroll
            for (int i = 0; i < 4; ++i) {
                int u = t + i * 256;
                uint32_t brow = (uint32_t)(u >> 4), bj = (uint32_t)(u & 15);
                cp_async16(bbn + brow * 256 + (swz(bj, brow) << 4),
                           g_W1b + (long long)(k0 + brow) * DD + bj * 8);
            }
        }
        cp_commit();
        cp_wait1();
        __syncthreads();

#pragma unroll
        for (int kk = 0; kk < 4; ++kk) {
            uint32_t arow = (uint32_t)lr16;
            uint32_t aj = (uint32_t)(kk * 2 + hi);
            uint32_t a0, a1, a2, a3;
            ldmatrix_x4(a0, a1, a2, a3, abuf + arow * 128 + (swz8(aj, arow) << 4));
            uint32_t lrow = (uint32_t)(kk * 16 + lr16);
            uint32_t rowb = bbuf + lrow * 256;
            uint32_t j2 = (uint32_t)(cg * 2 + hi);
            uint32_t v0, v1, v2, v3;
            ldmatrix_x4_trans(v0, v1, v2, v3, rowb + (swz(j2, lrow) << 4));
            mma16816(c[0], a0, a1, a2, a3, v0, v1);
            mma16816(c[1], a0, a1, a2, a3, v2, v3);
        }
        __syncthreads();
    }

    // x = elu(acc + b1) -> xs
    int row_lo = qr, row_hi = qr + 8;
#pragma unroll
    for (int j = 0; j < 2; ++j) {
        int cb = cg * 16 + j * 8 + ko;
        float2 bv = *(const float2*)&b1[cb];
        xs[row_lo * 132 + cb] = eluf(c[j][0] + bv.x);
        xs[row_lo * 132 + cb + 1] = eluf(c[j][1] + bv.y);
        xs[row_hi * 132 + cb] = eluf(c[j][2] + bv.x);
        xs[row_hi * 132 + cb + 1] = eluf(c[j][3] + bv.y);
    }
    __syncthreads();

    // LN: warp w handles rows w*2, w*2+1
    int e2 = lane * 4;
    float4 gg = *(const float4*)&gamma[e2];
    float4 be = *(const float4*)&beta[e2];
#pragma unroll
    for (int rr = 0; rr < 2; ++rr) {
        int row = w * 2 + rr;
        int n = n0 + row;
        float4 xv = *(const float4*)&xs[row * 132 + e2];
        float4 nd = *(const float4*)&nodes[n * DD + e2];
        float4 y = make_float4(nd.x + xv.x, nd.y + xv.y, nd.z + xv.z, nd.w + xv.w);
        float s = y.x + y.y + y.z + y.w;
        float q = y.x * y.x + y.y * y.y + y.z * y.z + y.w * y.w;
#pragma unroll
        for (int o = 16; o; o >>= 1) {
            s += __shfl_xor_sync(0xffffffffu, s, o);
            q += __shfl_xor_sync(0xffffffffu, q, o);
        }
        float mu = s * (1.f / 128.f);
        float var = q * (1.f / 128.f) - mu * mu;
        float rsx = rsqrtf(var + EPSLN);
        float4 o4;
        o4.x = (y.x - mu) * rsx * gg.x + be.x;
        o4.y = (y.y - mu) * rsx * gg.y + be.y;
        o4.z = (y.z - mu) * rsx * gg.z + be.z;
        o4.w = (y.w - mu) * rsx * gg.w + be.w;
        *(float4*)&out[n * DD + e2] = o4;
    }
}

extern "C" void kernel_launch(void* const* d_in, const int* in_sizes, int n_in,
                              void* d_out, int out_size) {
    const float* nodes = (const float*)d_in[0];
    const int* adj = (const int*)d_in[1];
    const float* W = (const float*)d_in[2];
    const float* a1 = (const float*)d_in[3];
    const float* a2 = (const float*)d_in[4];
    const float* W1 = (const float*)d_in[5];
    const float* b1 = (const float*)d_in[6];
    const float* gamma = (const float*)d_in[7];
    const float* beta = (const float*)d_in[8];
    float* out = (float*)d_out;

    cudaFuncSetAttribute(k_attn, cudaFuncAttributeMaxDynamicSharedMemorySize, ATTN_SMEM);
    cudaFuncSetAttribute(k_wh_mma, cudaFuncAttributeMaxDynamicSharedMemorySize, WH_SMEM);
    cudaFuncSetAttribute(k_final_mma, cudaFuncAttributeMaxDynamicSharedMemorySize, FIN_SMEM);

    k_pre<<<NN + 256, 256>>>(nodes, W, W1, adj);
    k_wh_mma<<<dim3(NN / 128, HH), 256, WH_SMEM>>>(a1, a2);
    k_attn<<<dim3(HH, NN / 128), 256, ATTN_SMEM>>>();
    k_final_mma<<<NN / 16, 256, FIN_SMEM>>>(nodes, b1, gamma, beta, out);  // 4th -> profiled
}

// round 16
// speedup vs baseline: 1.1139x; 1.1139x over previous
#include <cuda_runtime.h>
#include <cuda_bf16.h>
#include <cstdint>

#define NN 4096
#define DD 128
#define HH 8
#define ALPHA 0.2f
#define EPSLN 1e-5f

// ---------------- scratch ----------------
__device__ __nv_bfloat16 g_Whb[HH * NN * DD];    // [h][m][e] bf16 (attn values)
__device__ __nv_bfloat16 g_nodesb[NN * DD];      // nodes bf16
__device__ __nv_bfloat16 g_Wb[HH * DD * DD];     // W bf16 [h][d][e]
__device__ __nv_bfloat16 g_W1b[HH * DD * DD];    // W1 bf16 [1024][128]
__device__ __nv_bfloat16 g_attnb[NN * HH * DD];  // cat = elu(attn) bf16 [n][h*128+e]
__device__ float2 g_eq1[HH * NN];                // (e^{f1}, e^{0.2 f1})
__device__ float2 g_eq2[HH * NN];                // (e^{f2}, e^{0.2 f2})
__device__ unsigned g_adjbits[NN * (NN / 32)];   // 2MB bitmask

// ---------------- helpers ----------------
__device__ __forceinline__ uint32_t smem_u32(const void* p) {
    uint32_t a;
    asm("{ .reg .u64 t; cvta.to.shared.u64 t, %1; cvt.u32.u64 %0, t; }" : "=r"(a) : "l"(p));
    return a;
}
__device__ __forceinline__ void cp_async16(uint32_t sdst, const void* gsrc) {
    asm volatile("cp.async.cg.shared.global [%0], [%1], 16;" :: "r"(sdst), "l"(gsrc) : "memory");
}
__device__ __forceinline__ void cp_commit() {
    asm volatile("cp.async.commit_group;" ::: "memory");
}
__device__ __forceinline__ void cp_wait0() {
    asm volatile("cp.async.wait_group 0;" ::: "memory");
}
__device__ __forceinline__ void cp_wait1() {
    asm volatile("cp.async.wait_group 1;" ::: "memory");
}
__device__ __forceinline__ void ldmatrix_x4(uint32_t& b0, uint32_t& b1, uint32_t& b2,
                                            uint32_t& b3, uint32_t addr) {
    asm volatile("ldmatrix.sync.aligned.m8n8.x4.shared.b16 {%0,%1,%2,%3}, [%4];"
                 : "=r"(b0), "=r"(b1), "=r"(b2), "=r"(b3) : "r"(addr));
}
__device__ __forceinline__ void ldmatrix_x4_trans(uint32_t& b0, uint32_t& b1, uint32_t& b2,
                                                  uint32_t& b3, uint32_t addr) {
    asm volatile("ldmatrix.sync.aligned.m8n8.x4.trans.shared.b16 {%0,%1,%2,%3}, [%4];"
                 : "=r"(b0), "=r"(b1), "=r"(b2), "=r"(b3) : "r"(addr));
}
__device__ __forceinline__ void mma16816(float* c, uint32_t a0, uint32_t a1, uint32_t a2,
                                         uint32_t a3, uint32_t b0, uint32_t b1) {
    asm volatile(
        "mma.sync.aligned.m16n8k16.row.col.f32.bf16.bf16.f32 "
        "{%0,%1,%2,%3}, {%4,%5,%6,%7}, {%8,%9}, {%0,%1,%2,%3};"
        : "+f"(c[0]), "+f"(c[1]), "+f"(c[2]), "+f"(c[3])
        : "r"(a0), "r"(a1), "r"(a2), "r"(a3), "r"(b0), "r"(b1));
}
// swizzled 16B-chunk index: 256B rows (16 chunks) and 128B rows (8 chunks)
__device__ __forceinline__ uint32_t swz(uint32_t j, uint32_t row) {
    return (j & 8u) | ((j ^ row) & 7u);
}
__device__ __forceinline__ uint32_t swz8(uint32_t j, uint32_t row) {
    return (j ^ row) & 7u;
}
__device__ __forceinline__ float eluf(float v) { return v > 0.f ? v : expm1f(v); }

// ============================================================
// K_pre: fused front-end. Blocks [0,4096): adj bits (uint4 loads + nibble
// assembly, same bit semantics); [4096,4352): bf16 casts.
// ============================================================
__global__ void __launch_bounds__(256) k_pre(const float* __restrict__ nodes,
                                             const float* __restrict__ W,
                                             const float* __restrict__ W1,
                                             const int* __restrict__ adj) {
    int b = blockIdx.x;
    int t = threadIdx.x;
    if (b < NN) {
        __shared__ unsigned char nib[4][256];
        int n = b;
        const int4* arow = (const int4*)(adj + (long long)n * NN);
#pragma unroll
        for (int pass = 0; pass < 4; ++pass) {
            int4 v = arow[pass * 256 + t];
            unsigned nb = (v.x > 0 ? 1u : 0u) | (v.y > 0 ? 2u : 0u) |
                          (v.z > 0 ? 4u : 0u) | (v.w > 0 ? 8u : 0u);
            nib[pass][t] = (unsigned char)nb;
        }
        __syncthreads();
        if (t < 128) {
            int pass = t >> 5, wi = t & 31;
            const unsigned char* p = &nib[pass][wi * 8];
            unsigned wd = 0;
#pragma unroll
            for (int i = 0; i < 8; ++i) wd |= ((unsigned)p[i]) << (4 * i);
            g_adjbits[n * (NN / 32) + pass * 32 + wi] = wd;
        }
    } else {
        int cb = b - NN;                      // 0..255
        int idx = cb * 256 + t;
        for (int i = idx; i < (NN * DD) / 2; i += 256 * 256) {
            float2 v = *(const float2*)&nodes[i * 2];
            __nv_bfloat162 bb = __floats2bfloat162_rn(v.x, v.y);
            *(uint32_t*)&g_nodesb[i * 2] = *(uint32_t*)&bb;
        }
        for (int i = idx; i < (HH * DD * DD) / 2; i += 256 * 256) {
            float2 v = *(const float2*)&W[i * 2];
            __nv_bfloat162 bb = __floats2bfloat162_rn(v.x, v.y);
            *(uint32_t*)&g_Wb[i * 2] = *(uint32_t*)&bb;
            float2 v1 = *(const float2*)&W1[i * 2];
            __nv_bfloat162 b1v = __floats2bfloat162_rn(v1.x, v1.y);
            *(uint32_t*)&g_W1b[i * 2] = *(uint32_t*)&b1v;
        }
    }
}

// ============================================================
// K_wh_mma: Wh[h] = nodes @ W[h] on tensor cores -> bf16 [h][m][e].
// Epilogue also computes f1 = Wh·a1, f2 = Wh·a2 from the fp32 accumulators
// (quad shfl-reduce) and writes (e^f, e^{0.2f}) pairs.
// ============================================================
#define WH_SMEM (65536 + 1024)
__global__ void __launch_bounds__(256, 2) k_wh_mma(const float* __restrict__ a1,
                                                   const float* __restrict__ a2) {
    extern __shared__ char smem[];
    uint32_t sbase = smem_u32(smem);
    uint32_t abase = sbase;
    uint32_t wbase = sbase + 32768;
    float* a1s = (float*)(smem + 65536);
    float* a2s = (float*)(smem + 65536 + 512);
    int h = blockIdx.y;
    int n0 = blockIdx.x * 128;
    int t = threadIdx.x;
    int lane = t & 31, w = t >> 5;

#pragma unroll
    for (int i = 0; i < 8; ++i) {
        int u = t + i * 256;  // 0..2047
        uint32_t row = u >> 4, j = u & 15;
        cp_async16(abase + row * 256 + (swz(j, row) << 4),
                   g_nodesb + (long long)(n0 + row) * DD + j * 8);
        cp_async16(wbase + row * 256 + (swz(j, row) << 4),
                   g_Wb + (long long)h * DD * DD + row * DD + j * 8);
    }
    if (t < 128) {
        a1s[t] = a1[h * DD + t];
        a2s[t] = a2[h * DD + t];
    }
    cp_commit();
    cp_wait0();
    __syncthreads();

    int qr = lane >> 2, ko = (lane & 3) * 2;
    int lr16 = lane & 15, hi = lane >> 4;
    float c[16][4];
#pragma unroll
    for (int j = 0; j < 16; ++j) c[j][0] = c[j][1] = c[j][2] = c[j][3] = 0.f;

#pragma unroll
    for (int k = 0; k < 8; ++k) {
        uint32_t arow = (uint32_t)(w * 16 + lr16);
        uint32_t aj = (uint32_t)(k * 2 + hi);
        uint32_t a0, a1r, a2r, a3;
        ldmatrix_x4(a0, a1r, a2r, a3, abase + arow * 256 + (swz(aj, arow) << 4));
        uint32_t lrow = (uint32_t)(k * 16 + lr16);
        uint32_t rowb = wbase + lrow * 256;
#pragma unroll
        for (int jj = 0; jj < 8; ++jj) {
            uint32_t j2 = (uint32_t)(jj * 2 + hi);
            uint32_t v0, v1, v2, v3;
            ldmatrix_x4_trans(v0, v1, v2, v3, rowb + (swz(j2, lrow) << 4));
            mma16816(c[jj * 2], a0, a1r, a2r, a3, v0, v1);
            mma16816(c[jj * 2 + 1], a0, a1r, a2r, a3, v2, v3);
        }
    }

    int gn0 = n0 + w * 16 + qr;
    __nv_bfloat16* o0 = &g_Whb[((long long)h * NN + gn0) * DD];
    __nv_bfloat16* o1 = &g_Whb[((long long)h * NN + gn0 + 8) * DD];
#pragma unroll
    for (int j = 0; j < 16; ++j) {
        __nv_bfloat162 v0 = __floats2bfloat162_rn(c[j][0], c[j][1]);
        __nv_bfloat162 v1 = __floats2bfloat162_rn(c[j][2], c[j][3]);
        *(uint32_t*)&o0[j * 8 + ko] = *(uint32_t*)&v0;
        *(uint32_t*)&o1[j * 8 + ko] = *(uint32_t*)&v1;
    }

    // ---- f epilogue: f = Wh·a (rows gn0, gn0+8) ----
    float f1a = 0.f, f1b = 0.f, f2a = 0.f, f2b = 0.f;
#pragma unroll
    for (int j = 0; j < 16; ++j) {
        float a1lo = a1s[j * 8 + ko], a1hi = a1s[j * 8 + ko + 1];
        float a2lo = a2s[j * 8 + ko], a2hi = a2s[j * 8 + ko + 1];
        f1a += c[j][0] * a1lo + c[j][1] * a1hi;
        f1b += c[j][2] * a1lo + c[j][3] * a1hi;
        f2a += c[j][0] * a2lo + c[j][1] * a2hi;
        f2b += c[j][2] * a2lo + c[j][3] * a2hi;
    }
#pragma unroll
    for (int o = 1; o <= 2; o <<= 1) {
        f1a += __shfl_xor_sync(0xffffffffu, f1a, o);
        f1b += __shfl_xor_sync(0xffffffffu, f1b, o);
        f2a += __shfl_xor_sync(0xffffffffu, f2a, o);
        f2b += __shfl_xor_sync(0xffffffffu, f2b, o);
    }
    if ((lane & 3) == 0) {
        g_eq1[h * NN + gn0] = make_float2(__expf(f1a), __expf(ALPHA * f1a));
        g_eq2[h * NN + gn0] = make_float2(__expf(f2a), __expf(ALPHA * f2a));
        g_eq1[h * NN + gn0 + 8] = make_float2(__expf(f1b), __expf(ALPHA * f1b));
        g_eq2[h * NN + gn0 + 8] = make_float2(__expf(f2b), __expf(ALPHA * f2b));
    }
}

// ============================================================
// K_attn: softmax-agg via mma.sync bf16 (R12-proven: KC=128, ones-MMA rowsum).
// p = bit ? max(e1*e2, q1*q2) : 0   (== exp(lrelu(f1+f2)), FMNMX, no branch).
// Epilogue: elu(normalized) -> bf16 cat [n][h*128+e].
// ============================================================
#define KC 128
#define BBYTES (KC * 256)         // 32KB per B buffer
#define SM_EQ2 (2 * BBYTES)       // (e2,q2)[4096] at 64KB
#define ATTN_SMEM (SM_EQ2 + NN * 8)

__global__ void __launch_bounds__(256, 2) k_attn() {
    extern __shared__ char smem[];
    uint32_t sbase = smem_u32(smem);
    float* eq2s = (float*)(smem + SM_EQ2);
    int h = blockIdx.x;
    int n0 = blockIdx.y * 128;
    int t = threadIdx.x;
    int lane = t & 31, w = t >> 5;

    // ---- preload B chunk 0 (128 m-rows x 128 cols = 32KB) ----
    const __nv_bfloat16* whb = &g_Whb[(long long)h * NN * DD];
#pragma unroll
    for (int i = 0; i < 8; ++i) {
        int u = t + i * 256;  // 0..2047
        uint32_t row = u >> 4, j = u & 15;
        cp_async16(sbase + row * 256 + (swz(j, row) << 4),
                   whb + (long long)row * DD + j * 8);
    }
    cp_commit();
    // ---- stage (e2,q2) pairs into smem ----
    {
        const float4* src = (const float4*)(g_eq2 + h * NN);
        float4* dst = (float4*)eq2s;
        for (int i = t; i < NN / 2; i += 256) dst[i] = src[i];
    }

    int qr = lane >> 2;          // 0..7
    int ko = (lane & 3) * 2;     // 0,2,4,6
    int gn0 = n0 + w * 16 + qr;
    int gn1 = gn0 + 8;
    float2 eqA = g_eq1[h * NN + gn0];
    float2 eqB = g_eq1[h * NN + gn1];
    const uint4* bp0 = (const uint4*)&g_adjbits[(long long)gn0 * (NN / 32)];
    const uint4* bp1 = (const uint4*)&g_adjbits[(long long)gn1 * (NN / 32)];
    float c[16][4];
#pragma unroll
    for (int j = 0; j < 16; ++j) c[j][0] = c[j][1] = c[j][2] = c[j][3] = 0.f;
    float crs[4] = {0.f, 0.f, 0.f, 0.f};
    __nv_bfloat162 one2 = __floats2bfloat162_rn(1.f, 1.f);
    uint32_t ONES = *(uint32_t*)&one2;

    int lr16 = lane & 15;
    int hi = lane >> 4;

    for (int ch = 0; ch < NN / KC; ++ch) {
        uint32_t bcur = sbase + (ch & 1) * BBYTES;
        if (ch + 1 < NN / KC) {
            uint32_t bnext = sbase + ((ch + 1) & 1) * BBYTES;
            const __nv_bfloat16* src = whb + (long long)(ch + 1) * KC * DD;
#pragma unroll
            for (int i = 0; i < 8; ++i) {
                int u = t + i * 256;
                uint32_t row = u >> 4, j = u & 15;
                cp_async16(bnext + row * 256 + (swz(j, row) << 4),
                           src + (long long)row * DD + j * 8);
            }
        }
        cp_commit();
        cp_wait1();
        __syncthreads();

        uint4 bw0 = bp0[ch], bw1 = bp1[ch];

#pragma unroll
        for (int s = 0; s < 8; ++s) {
            int mb = ch * KC + s * 16;
            float4 mA = *(const float4*)&eq2s[2 * (mb + ko)];       // (e2,q2) m, m+1
            float4 mB = *(const float4*)&eq2s[2 * (mb + ko + 8)];   // m+8, m+9
            uint32_t w0 = (s < 2) ? bw0.x : (s < 4) ? bw0.y : (s < 6) ? bw0.z : bw0.w;
            uint32_t w1 = (s < 2) ? bw1.x : (s < 4) ? bw1.y : (s < 6) ? bw1.z : bw1.w;
            uint32_t t0 = (w0 >> ((s & 1) * 16)) >> ko;
            uint32_t t1 = (w1 >> ((s & 1) * 16)) >> ko;
            float v00 = fmaxf(eqA.x * mA.x, eqA.y * mA.y);
            float v01 = fmaxf(eqA.x * mA.z, eqA.y * mA.w);
            float v02 = fmaxf(eqA.x * mB.x, eqA.y * mB.y);
            float v03 = fmaxf(eqA.x * mB.z, eqA.y * mB.w);
            float v10 = fmaxf(eqB.x * mA.x, eqB.y * mA.y);
            float v11 = fmaxf(eqB.x * mA.z, eqB.y * mA.w);
            float v12 = fmaxf(eqB.x * mB.x, eqB.y * mB.y);
            float v13 = fmaxf(eqB.x * mB.z, eqB.y * mB.w);
            float p00 = (t0 & 1u) ? v00 : 0.f;
            float p01 = (t0 & 2u) ? v01 : 0.f;
            float p02 = (t0 & 0x100u) ? v02 : 0.f;
            float p03 = (t0 & 0x200u) ? v03 : 0.f;
            float p10 = (t1 & 1u) ? v10 : 0.f;
            float p11 = (t1 & 2u) ? v11 : 0.f;
            float p12 = (t1 & 0x100u) ? v12 : 0.f;
            float p13 = (t1 & 0x200u) ? v13 : 0.f;
            __nv_bfloat162 A0 = __floats2bfloat162_rn(p00, p01);
            __nv_bfloat162 A1 = __floats2bfloat162_rn(p10, p11);
            __nv_bfloat162 A2 = __floats2bfloat162_rn(p02, p03);
            __nv_bfloat162 A3 = __floats2bfloat162_rn(p12, p13);
            uint32_t a0 = *(uint32_t*)&A0, a1 = *(uint32_t*)&A1;
            uint32_t a2 = *(uint32_t*)&A2, a3 = *(uint32_t*)&A3;

            uint32_t lrow = (uint32_t)(s * 16 + lr16);
            uint32_t rowb = bcur + lrow * 256;
#pragma unroll
            for (int jj = 0; jj < 8; ++jj) {
                uint32_t j2 = (uint32_t)(jj * 2 + hi);
                uint32_t addr = rowb + (swz(j2, lrow) << 4);
                uint32_t v0, v1, v2, v3;
                ldmatrix_x4_trans(v0, v1, v2, v3, addr);
                mma16816(c[jj * 2], a0, a1, a2, a3, v0, v1);
                mma16816(c[jj * 2 + 1], a0, a1, a2, a3, v2, v3);
            }
            // row-sum MMA against ones
            mma16816(crs, a0, a1, a2, a3, ONES, ONES);
        }
        __syncthreads();
    }

    float inv0 = 1.f / crs[0], inv1 = 1.f / crs[2];

    // epilogue: elu(normalized) -> bf16 cat [n][h*128+e]
    __nv_bfloat16* o0 = &g_attnb[(long long)gn0 * (HH * DD) + h * DD];
    __nv_bfloat16* o1 = &g_attnb[(long long)gn1 * (HH * DD) + h * DD];
#pragma unroll
    for (int j = 0; j < 16; ++j) {
        float v0 = eluf(c[j][0] * inv0);
        float v1 = eluf(c[j][1] * inv0);
        float v2 = eluf(c[j][2] * inv1);
        float v3 = eluf(c[j][3] * inv1);
        __nv_bfloat162 b0v = __floats2bfloat162_rn(v0, v1);
        __nv_bfloat162 b1v = __floats2bfloat162_rn(v2, v3);
        *(uint32_t*)&o0[j * 8 + ko] = *(uint32_t*)&b0v;
        *(uint32_t*)&o1[j * 8 + ko] = *(uint32_t*)&b1v;
    }
}

// ============================================================
// K_final_mma: x = elu(cat @ W1 + b1) on tensor cores; out = LN(nodes+x).
// R12-proven: 32-row CTAs, 8 warps = 2 row-groups x 4 col-groups.
// ============================================================
#define SMF_A 0                      // 2 x 4KB
#define SMF_B 8192                   // 2 x 16KB
#define SMF_X 40960                  // 32 x 132 floats
#define FIN_SMEM (40960 + 32 * 132 * 4)

__global__ void __launch_bounds__(256, 2) k_final_mma(const float* __restrict__ nodes,
                                                      const float* __restrict__ b1,
                                                      const float* __restrict__ gamma,
                                                      const float* __restrict__ beta,
                                                      float* __restrict__ out) {
    extern __shared__ char smem[];
    uint32_t sbase = smem_u32(smem);
    float* xs = (float*)(smem + SMF_X);
    int n0 = blockIdx.x * 32;
    int t = threadIdx.x;
    int lane = t & 31, w = t >> 5;
    int rg = w >> 2, cg = w & 3;

    // prefetch chunk 0
    {
        uint32_t row = (uint32_t)(t >> 3), j = (uint32_t)(t & 7);
        cp_async16(sbase + SMF_A + row * 128 + (swz8(j, row) << 4),
                   g_attnb + (long long)(n0 + row) * (HH * DD) + j * 8);
#pragma unroll
        for (int i = 0; i < 4; ++i) {
            int u = t + i * 256;
            uint32_t brow = (uint32_t)(u >> 4), bj = (uint32_t)(u & 15);
            cp_async16(sbase + SMF_B + brow * 256 + (swz(bj, brow) << 4),
                       g_W1b + (long long)brow * DD + bj * 8);
        }
    }
    cp_commit();

    int qr = lane >> 2, ko = (lane & 3) * 2;
    int lr16 = lane & 15, hi = lane >> 4;
    float c[4][4];
#pragma unroll
    for (int j = 0; j < 4; ++j) c[j][0] = c[j][1] = c[j][2] = c[j][3] = 0.f;

    for (int ch = 0; ch < 16; ++ch) {
        uint32_t abuf = sbase + SMF_A + (ch & 1) * 4096;
        uint32_t bbuf = sbase + SMF_B + (ch & 1) * 16384;
        if (ch + 1 < 16) {
            uint32_t abn = sbase + SMF_A + ((ch + 1) & 1) * 4096;
            uint32_t bbn = sbase + SMF_B + ((ch + 1) & 1) * 16384;
            int k0 = (ch + 1) * 64;
            uint32_t row = (uint32_t)(t >> 3), j = (uint32_t)(t & 7);
            cp_async16(abn + row * 128 + (swz8(j, row) << 4),
                       g_attnb + (long long)(n0 + row) * (HH * DD) + k0 + j * 8);
#pragma unroll
            for (int i = 0; i < 4; ++i) {
                int u = t + i * 256;
                uint32_t brow = (uint32_t)(u >> 4), bj = (uint32_t)(u & 15);
                cp_async16(bbn + brow * 256 + (swz(bj, brow) << 4),
                           g_W1b + (long long)(k0 + brow) * DD + bj * 8);
            }
        }
        cp_commit();
        cp_wait1();
        __syncthreads();

#pragma unroll
        for (int kk = 0; kk < 4; ++kk) {
            uint32_t arow = (uint32_t)(rg * 16 + lr16);
            uint32_t aj = (uint32_t)(kk * 2 + hi);
            uint32_t a0, a1, a2, a3;
            ldmatrix_x4(a0, a1, a2, a3, abuf + arow * 128 + (swz8(aj, arow) << 4));
            uint32_t lrow = (uint32_t)(kk * 16 + lr16);
            uint32_t rowb = bbuf + lrow * 256;
#pragma unroll
            for (int jj = 0; jj < 2; ++jj) {
                uint32_t j2 = (uint32_t)(cg * 4 + jj * 2 + hi);
                uint32_t v0, v1, v2, v3;
                ldmatrix_x4_trans(v0, v1, v2, v3, rowb + (swz(j2, lrow) << 4));
                mma16816(c[jj * 2], a0, a1, a2, a3, v0, v1);
                mma16816(c[jj * 2 + 1], a0, a1, a2, a3, v2, v3);
            }
        }
        __syncthreads();
    }

    // x = elu(acc + b1) -> xs
    int row_lo = rg * 16 + qr, row_hi = row_lo + 8;
#pragma unroll
    for (int j = 0; j < 4; ++j) {
        int cb = cg * 32 + j * 8 + ko;
        float2 bv = *(const float2*)&b1[cb];
        xs[row_lo * 132 + cb] = eluf(c[j][0] + bv.x);
        xs[row_lo * 132 + cb + 1] = eluf(c[j][1] + bv.y);
        xs[row_hi * 132 + cb] = eluf(c[j][2] + bv.x);
        xs[row_hi * 132 + cb + 1] = eluf(c[j][3] + bv.y);
    }
    __syncthreads();

    // LN: warp w handles rows w*4..w*4+3
    int e2 = lane * 4;
    float4 gg = *(const float4*)&gamma[e2];
    float4 be = *(const float4*)&beta[e2];
#pragma unroll
    for (int rr = 0; rr < 4; ++rr) {
        int row = w * 4 + rr;
        int n = n0 + row;
        float4 xv = *(const float4*)&xs[row * 132 + e2];
        float4 nd = *(const float4*)&nodes[n * DD + e2];
        float4 y = make_float4(nd.x + xv.x, nd.y + xv.y, nd.z + xv.z, nd.w + xv.w);
        float s = y.x + y.y + y.z + y.w;
        float q = y.x * y.x + y.y * y.y + y.z * y.z + y.w * y.w;
#pragma unroll
        for (int o = 16; o; o >>= 1) {
            s += __shfl_xor_sync(0xffffffffu, s, o);
            q += __shfl_xor_sync(0xffffffffu, q, o);
        }
        float mu = s * (1.f / 128.f);
        float var = q * (1.f / 128.f) - mu * mu;
        float rsx = rsqrtf(var + EPSLN);
        float4 o4;
        o4.x = (y.x - mu) * rsx * gg.x + be.x;
        o4.y = (y.y - mu) * rsx * gg.y + be.y;
        o4.z = (y.z - mu) * rsx * gg.z + be.z;
        o4.w = (y.w - mu) * rsx * gg.w + be.w;
        *(float4*)&out[n * DD + e2] = o4;
    }
}

extern "C" void kernel_launch(void* const* d_in, const int* in_sizes, int n_in,
                              void* d_out, int out_size) {
    const float* nodes = (const float*)d_in[0];
    const int* adj = (const int*)d_in[1];
    const float* W = (const float*)d_in[2];
    const float* a1 = (const float*)d_in[3];
    const float* a2 = (const float*)d_in[4];
    const float* W1 = (const float*)d_in[5];
    const float* b1 = (const float*)d_in[6];
    const float* gamma = (const float*)d_in[7];
    const float* beta = (const float*)d_in[8];
    float* out = (float*)d_out;

    cudaFuncSetAttribute(k_attn, cudaFuncAttributeMaxDynamicSharedMemorySize, ATTN_SMEM);
    cudaFuncSetAttribute(k_wh_mma, cudaFuncAttributeMaxDynamicSharedMemorySize, WH_SMEM);
    cudaFuncSetAttribute(k_final_mma, cudaFuncAttributeMaxDynamicSharedMemorySize, FIN_SMEM);

    k_pre<<<NN + 256, 256>>>(nodes, W, W1, adj);
    k_wh_mma<<<dim3(NN / 128, HH), 256, WH_SMEM>>>(a1, a2);
    k_attn<<<dim3(HH, NN / 128), 256, ATTN_SMEM>>>();
    k_final_mma<<<NN / 32, 256, FIN_SMEM>>>(nodes, b1, gamma, beta, out);
}

// round 17
// speedup vs baseline: 1.1214x; 1.0067x over previous
#include <cuda_runtime.h>
#include <cuda_bf16.h>
#include <cstdint>

#define NN 4096
#define DD 128
#define HH 8
#define ALPHA 0.2f
#define EPSLN 1e-5f

// ---------------- scratch ----------------
__device__ __nv_bfloat16 g_Whb[HH * NN * DD];    // [h][m][e] bf16 (attn values)
__device__ __nv_bfloat16 g_nodesb[NN * DD];      // nodes bf16
__device__ __nv_bfloat16 g_Wb[HH * DD * DD];     // W bf16 [h][d][e]
__device__ __nv_bfloat16 g_W1b[HH * DD * DD];    // W1 bf16 [1024][128]
__device__ __nv_bfloat16 g_attnb[NN * HH * DD];  // cat = elu(attn) bf16 [n][h*128+e]
__device__ float2 g_eq1[HH * NN];                // (e^{f1}, e^{0.2 f1})
__device__ float2 g_eq2[HH * NN];                // (e^{f2}, e^{0.2 f2})
__device__ unsigned g_adjbits[NN * (NN / 32)];   // 2MB bitmask

// ---------------- helpers ----------------
__device__ __forceinline__ uint32_t smem_u32(const void* p) {
    uint32_t a;
    asm("{ .reg .u64 t; cvta.to.shared.u64 t, %1; cvt.u32.u64 %0, t; }" : "=r"(a) : "l"(p));
    return a;
}
__device__ __forceinline__ void cp_async16(uint32_t sdst, const void* gsrc) {
    asm volatile("cp.async.cg.shared.global [%0], [%1], 16;" :: "r"(sdst), "l"(gsrc) : "memory");
}
__device__ __forceinline__ void cp_commit() {
    asm volatile("cp.async.commit_group;" ::: "memory");
}
__device__ __forceinline__ void cp_wait0() {
    asm volatile("cp.async.wait_group 0;" ::: "memory");
}
__device__ __forceinline__ void cp_wait1() {
    asm volatile("cp.async.wait_group 1;" ::: "memory");
}
__device__ __forceinline__ void ldmatrix_x4(uint32_t& b0, uint32_t& b1, uint32_t& b2,
                                            uint32_t& b3, uint32_t addr) {
    asm volatile("ldmatrix.sync.aligned.m8n8.x4.shared.b16 {%0,%1,%2,%3}, [%4];"
                 : "=r"(b0), "=r"(b1), "=r"(b2), "=r"(b3) : "r"(addr));
}
__device__ __forceinline__ void ldmatrix_x4_trans(uint32_t& b0, uint32_t& b1, uint32_t& b2,
                                                  uint32_t& b3, uint32_t addr) {
    asm volatile("ldmatrix.sync.aligned.m8n8.x4.trans.shared.b16 {%0,%1,%2,%3}, [%4];"
                 : "=r"(b0), "=r"(b1), "=r"(b2), "=r"(b3) : "r"(addr));
}
__device__ __forceinline__ void mma16816(float* c, uint32_t a0, uint32_t a1, uint32_t a2,
                                         uint32_t a3, uint32_t b0, uint32_t b1) {
    asm volatile(
        "mma.sync.aligned.m16n8k16.row.col.f32.bf16.bf16.f32 "
        "{%0,%1,%2,%3}, {%4,%5,%6,%7}, {%8,%9}, {%0,%1,%2,%3};"
        : "+f"(c[0]), "+f"(c[1]), "+f"(c[2]), "+f"(c[3])
        : "r"(a0), "r"(a1), "r"(a2), "r"(a3), "r"(b0), "r"(b1));
}
// swizzled 16B-chunk index: 256B rows (16 chunks) and 128B rows (8 chunks)
__device__ __forceinline__ uint32_t swz(uint32_t j, uint32_t row) {
    return (j & 8u) | ((j ^ row) & 7u);
}
__device__ __forceinline__ uint32_t swz8(uint32_t j, uint32_t row) {
    return (j ^ row) & 7u;
}
__device__ __forceinline__ float eluf(float v) { return v > 0.f ? v : expm1f(v); }

// ============================================================
// K_pre: fused front-end. Blocks [0,4096): adj bits (uint4 loads + nibble
// assembly, same bit semantics); [4096,4352): bf16 casts.
// ============================================================
__global__ void __launch_bounds__(256) k_pre(const float* __restrict__ nodes,
                                             const float* __restrict__ W,
                                             const float* __restrict__ W1,
                                             const int* __restrict__ adj) {
    int b = blockIdx.x;
    int t = threadIdx.x;
    if (b < NN) {
        __shared__ unsigned char nib[4][256];
        int n = b;
        const int4* arow = (const int4*)(adj + (long long)n * NN);
#pragma unroll
        for (int pass = 0; pass < 4; ++pass) {
            int4 v = arow[pass * 256 + t];
            unsigned nb = (v.x > 0 ? 1u : 0u) | (v.y > 0 ? 2u : 0u) |
                          (v.z > 0 ? 4u : 0u) | (v.w > 0 ? 8u : 0u);
            nib[pass][t] = (unsigned char)nb;
        }
        __syncthreads();
        if (t < 128) {
            int pass = t >> 5, wi = t & 31;
            const unsigned char* p = &nib[pass][wi * 8];
            unsigned wd = 0;
#pragma unroll
            for (int i = 0; i < 8; ++i) wd |= ((unsigned)p[i]) << (4 * i);
            g_adjbits[n * (NN / 32) + pass * 32 + wi] = wd;
        }
    } else {
        int cb = b - NN;                      // 0..255
        int idx = cb * 256 + t;
        for (int i = idx; i < (NN * DD) / 2; i += 256 * 256) {
            float2 v = *(const float2*)&nodes[i * 2];
            __nv_bfloat162 bb = __floats2bfloat162_rn(v.x, v.y);
            *(uint32_t*)&g_nodesb[i * 2] = *(uint32_t*)&bb;
        }
        for (int i = idx; i < (HH * DD * DD) / 2; i += 256 * 256) {
            float2 v = *(const float2*)&W[i * 2];
            __nv_bfloat162 bb = __floats2bfloat162_rn(v.x, v.y);
            *(uint32_t*)&g_Wb[i * 2] = *(uint32_t*)&bb;
            float2 v1 = *(const float2*)&W1[i * 2];
            __nv_bfloat162 b1v = __floats2bfloat162_rn(v1.x, v1.y);
            *(uint32_t*)&g_W1b[i * 2] = *(uint32_t*)&b1v;
        }
    }
}

// ============================================================
// K_wh_mma: Wh[h] = nodes @ W[h] on tensor cores -> bf16 [h][m][e].
// Epilogue also computes f1 = Wh·a1, f2 = Wh·a2 from the fp32 accumulators
// (quad shfl-reduce) and writes (e^f, e^{0.2f}) pairs.
// ============================================================
#define WH_SMEM (65536 + 1024)
__global__ void __launch_bounds__(256, 2) k_wh_mma(const float* __restrict__ a1,
                                                   const float* __restrict__ a2) {
    extern __shared__ char smem[];
    uint32_t sbase = smem_u32(smem);
    uint32_t abase = sbase;
    uint32_t wbase = sbase + 32768;
    float* a1s = (float*)(smem + 65536);
    float* a2s = (float*)(smem + 65536 + 512);
    int h = blockIdx.y;
    int n0 = blockIdx.x * 128;
    int t = threadIdx.x;
    int lane = t & 31, w = t >> 5;

#pragma unroll
    for (int i = 0; i < 8; ++i) {
        int u = t + i * 256;  // 0..2047
        uint32_t row = u >> 4, j = u & 15;
        cp_async16(abase + row * 256 + (swz(j, row) << 4),
                   g_nodesb + (long long)(n0 + row) * DD + j * 8);
        cp_async16(wbase + row * 256 + (swz(j, row) << 4),
                   g_Wb + (long long)h * DD * DD + row * DD + j * 8);
    }
    if (t < 128) {
        a1s[t] = a1[h * DD + t];
        a2s[t] = a2[h * DD + t];
    }
    cp_commit();
    cp_wait0();
    __syncthreads();

    int qr = lane >> 2, ko = (lane & 3) * 2;
    int lr16 = lane & 15, hi = lane >> 4;
    float c[16][4];
#pragma unroll
    for (int j = 0; j < 16; ++j) c[j][0] = c[j][1] = c[j][2] = c[j][3] = 0.f;

#pragma unroll
    for (int k = 0; k < 8; ++k) {
        uint32_t arow = (uint32_t)(w * 16 + lr16);
        uint32_t aj = (uint32_t)(k * 2 + hi);
        uint32_t a0, a1r, a2r, a3;
        ldmatrix_x4(a0, a1r, a2r, a3, abase + arow * 256 + (swz(aj, arow) << 4));
        uint32_t lrow = (uint32_t)(k * 16 + lr16);
        uint32_t rowb = wbase + lrow * 256;
#pragma unroll
        for (int jj = 0; jj < 8; ++jj) {
            uint32_t j2 = (uint32_t)(jj * 2 + hi);
            uint32_t v0, v1, v2, v3;
            ldmatrix_x4_trans(v0, v1, v2, v3, rowb + (swz(j2, lrow) << 4));
            mma16816(c[jj * 2], a0, a1r, a2r, a3, v0, v1);
            mma16816(c[jj * 2 + 1], a0, a1r, a2r, a3, v2, v3);
        }
    }

    int gn0 = n0 + w * 16 + qr;
    __nv_bfloat16* o0 = &g_Whb[((long long)h * NN + gn0) * DD];
    __nv_bfloat16* o1 = &g_Whb[((long long)h * NN + gn0 + 8) * DD];
#pragma unroll
    for (int j = 0; j < 16; ++j) {
        __nv_bfloat162 v0 = __floats2bfloat162_rn(c[j][0], c[j][1]);
        __nv_bfloat162 v1 = __floats2bfloat162_rn(c[j][2], c[j][3]);
        *(uint32_t*)&o0[j * 8 + ko] = *(uint32_t*)&v0;
        *(uint32_t*)&o1[j * 8 + ko] = *(uint32_t*)&v1;
    }

    // ---- f epilogue: f = Wh·a (rows gn0, gn0+8) ----
    float f1a = 0.f, f1b = 0.f, f2a = 0.f, f2b = 0.f;
#pragma unroll
    for (int j = 0; j < 16; ++j) {
        float a1lo = a1s[j * 8 + ko], a1hi = a1s[j * 8 + ko + 1];
        float a2lo = a2s[j * 8 + ko], a2hi = a2s[j * 8 + ko + 1];
        f1a += c[j][0] * a1lo + c[j][1] * a1hi;
        f1b += c[j][2] * a1lo + c[j][3] * a1hi;
        f2a += c[j][0] * a2lo + c[j][1] * a2hi;
        f2b += c[j][2] * a2lo + c[j][3] * a2hi;
    }
#pragma unroll
    for (int o = 1; o <= 2; o <<= 1) {
        f1a += __shfl_xor_sync(0xffffffffu, f1a, o);
        f1b += __shfl_xor_sync(0xffffffffu, f1b, o);
        f2a += __shfl_xor_sync(0xffffffffu, f2a, o);
        f2b += __shfl_xor_sync(0xffffffffu, f2b, o);
    }
    if ((lane & 3) == 0) {
        g_eq1[h * NN + gn0] = make_float2(__expf(f1a), __expf(ALPHA * f1a));
        g_eq2[h * NN + gn0] = make_float2(__expf(f2a), __expf(ALPHA * f2a));
        g_eq1[h * NN + gn0 + 8] = make_float2(__expf(f1b), __expf(ALPHA * f1b));
        g_eq2[h * NN + gn0 + 8] = make_float2(__expf(f2b), __expf(ALPHA * f2b));
    }
}

// ============================================================
// K_attn: softmax-agg via mma.sync bf16 (R12-proven: KC=128, ones-MMA rowsum).
// p = bit ? max(e1*e2, q1*q2) : 0   (== exp(lrelu(f1+f2)), FMNMX, no branch).
// Epilogue: elu(normalized) -> bf16 cat [n][h*128+e].
// ============================================================
#define KC 128
#define BBYTES (KC * 256)         // 32KB per B buffer
#define SM_EQ2 (2 * BBYTES)       // (e2,q2)[4096] at 64KB
#define ATTN_SMEM (SM_EQ2 + NN * 8)

__global__ void __launch_bounds__(256, 2) k_attn() {
    extern __shared__ char smem[];
    uint32_t sbase = smem_u32(smem);
    float* eq2s = (float*)(smem + SM_EQ2);
    int h = blockIdx.x;
    int n0 = blockIdx.y * 128;
    int t = threadIdx.x;
    int lane = t & 31, w = t >> 5;

    // ---- preload B chunk 0 (128 m-rows x 128 cols = 32KB) ----
    const __nv_bfloat16* whb = &g_Whb[(long long)h * NN * DD];
#pragma unroll
    for (int i = 0; i < 8; ++i) {
        int u = t + i * 256;  // 0..2047
        uint32_t row = u >> 4, j = u & 15;
        cp_async16(sbase + row * 256 + (swz(j, row) << 4),
                   whb + (long long)row * DD + j * 8);
    }
    cp_commit();
    // ---- stage (e2,q2) pairs into smem ----
    {
        const float4* src = (const float4*)(g_eq2 + h * NN);
        float4* dst = (float4*)eq2s;
        for (int i = t; i < NN / 2; i += 256) dst[i] = src[i];
    }

    int qr = lane >> 2;          // 0..7
    int ko = (lane & 3) * 2;     // 0,2,4,6
    int gn0 = n0 + w * 16 + qr;
    int gn1 = gn0 + 8;
    float2 eqA = g_eq1[h * NN + gn0];
    float2 eqB = g_eq1[h * NN + gn1];
    const uint4* bp0 = (const uint4*)&g_adjbits[(long long)gn0 * (NN / 32)];
    const uint4* bp1 = (const uint4*)&g_adjbits[(long long)gn1 * (NN / 32)];
    float c[16][4];
#pragma unroll
    for (int j = 0; j < 16; ++j) c[j][0] = c[j][1] = c[j][2] = c[j][3] = 0.f;
    float crs[4] = {0.f, 0.f, 0.f, 0.f};
    __nv_bfloat162 one2 = __floats2bfloat162_rn(1.f, 1.f);
    uint32_t ONES = *(uint32_t*)&one2;

    int lr16 = lane & 15;
    int hi = lane >> 4;

    for (int ch = 0; ch < NN / KC; ++ch) {
        uint32_t bcur = sbase + (ch & 1) * BBYTES;
        if (ch + 1 < NN / KC) {
            uint32_t bnext = sbase + ((ch + 1) & 1) * BBYTES;
            const __nv_bfloat16* src = whb + (long long)(ch + 1) * KC * DD;
#pragma unroll
            for (int i = 0; i < 8; ++i) {
                int u = t + i * 256;
                uint32_t row = u >> 4, j = u & 15;
                cp_async16(bnext + row * 256 + (swz(j, row) << 4),
                           src + (long long)row * DD + j * 8);
            }
        }
        cp_commit();
        cp_wait1();
        __syncthreads();

        uint4 bw0 = bp0[ch], bw1 = bp1[ch];

#pragma unroll
        for (int s = 0; s < 8; ++s) {
            int mb = ch * KC + s * 16;
            float4 mA = *(const float4*)&eq2s[2 * (mb + ko)];       // (e2,q2) m, m+1
            float4 mB = *(const float4*)&eq2s[2 * (mb + ko + 8)];   // m+8, m+9
            uint32_t w0 = (s < 2) ? bw0.x : (s < 4) ? bw0.y : (s < 6) ? bw0.z : bw0.w;
            uint32_t w1 = (s < 2) ? bw1.x : (s < 4) ? bw1.y : (s < 6) ? bw1.z : bw1.w;
            uint32_t t0 = (w0 >> ((s & 1) * 16)) >> ko;
            uint32_t t1 = (w1 >> ((s & 1) * 16)) >> ko;
            float v00 = fmaxf(eqA.x * mA.x, eqA.y * mA.y);
            float v01 = fmaxf(eqA.x * mA.z, eqA.y * mA.w);
            float v02 = fmaxf(eqA.x * mB.x, eqA.y * mB.y);
            float v03 = fmaxf(eqA.x * mB.z, eqA.y * mB.w);
            float v10 = fmaxf(eqB.x * mA.x, eqB.y * mA.y);
            float v11 = fmaxf(eqB.x * mA.z, eqB.y * mA.w);
            float v12 = fmaxf(eqB.x * mB.x, eqB.y * mB.y);
            float v13 = fmaxf(eqB.x * mB.z, eqB.y * mB.w);
            float p00 = (t0 & 1u) ? v00 : 0.f;
            float p01 = (t0 & 2u) ? v01 : 0.f;
            float p02 = (t0 & 0x100u) ? v02 : 0.f;
            float p03 = (t0 & 0x200u) ? v03 : 0.f;
            float p10 = (t1 & 1u) ? v10 : 0.f;
            float p11 = (t1 & 2u) ? v11 : 0.f;
            float p12 = (t1 & 0x100u) ? v12 : 0.f;
            float p13 = (t1 & 0x200u) ? v13 : 0.f;
            __nv_bfloat162 A0 = __floats2bfloat162_rn(p00, p01);
            __nv_bfloat162 A1 = __floats2bfloat162_rn(p10, p11);
            __nv_bfloat162 A2 = __floats2bfloat162_rn(p02, p03);
            __nv_bfloat162 A3 = __floats2bfloat162_rn(p12, p13);
            uint32_t a0 = *(uint32_t*)&A0, a1 = *(uint32_t*)&A1;
            uint32_t a2 = *(uint32_t*)&A2, a3 = *(uint32_t*)&A3;

            uint32_t lrow = (uint32_t)(s * 16 + lr16);
            uint32_t rowb = bcur + lrow * 256;
#pragma unroll
            for (int jj = 0; jj < 8; ++jj) {
                uint32_t j2 = (uint32_t)(jj * 2 + hi);
                uint32_t addr = rowb + (swz(j2, lrow) << 4);
                uint32_t v0, v1, v2, v3;
                ldmatrix_x4_trans(v0, v1, v2, v3, addr);
                mma16816(c[jj * 2], a0, a1, a2, a3, v0, v1);
                mma16816(c[jj * 2 + 1], a0, a1, a2, a3, v2, v3);
            }
            // row-sum MMA against ones
            mma16816(crs, a0, a1, a2, a3, ONES, ONES);
        }
        __syncthreads();
    }

    float inv0 = 1.f / crs[0], inv1 = 1.f / crs[2];

    // epilogue: elu(normalized) -> bf16 cat [n][h*128+e]
    __nv_bfloat16* o0 = &g_attnb[(long long)gn0 * (HH * DD) + h * DD];
    __nv_bfloat16* o1 = &g_attnb[(long long)gn1 * (HH * DD) + h * DD];
#pragma unroll
    for (int j = 0; j < 16; ++j) {
        float v0 = eluf(c[j][0] * inv0);
        float v1 = eluf(c[j][1] * inv0);
        float v2 = eluf(c[j][2] * inv1);
        float v3 = eluf(c[j][3] * inv1);
        __nv_bfloat162 b0v = __floats2bfloat162_rn(v0, v1);
        __nv_bfloat162 b1v = __floats2bfloat162_rn(v2, v3);
        *(uint32_t*)&o0[j * 8 + ko] = *(uint32_t*)&b0v;
        *(uint32_t*)&o1[j * 8 + ko] = *(uint32_t*)&b1v;
    }
}

// ============================================================
// K_final_mma: x = elu(cat @ W1 + b1) on tensor cores; out = LN(nodes+x).
// KC=128: 8 chunks (A 8KB + B 32KB each, double-buffered) -> half the
// serial wait/barrier chain of the KC=64 version. Same accumulation order.
// 32-row CTAs, 8 warps = 2 row-groups x 4 col-groups.
// ============================================================
#define SMF_A 0                      // 2 x 8KB
#define SMF_B 16384                  // 2 x 32KB
#define SMF_X 81920                  // 32 x 132 floats
#define FIN_SMEM (81920 + 32 * 132 * 4)

__global__ void __launch_bounds__(256, 2) k_final_mma(const float* __restrict__ nodes,
                                                      const float* __restrict__ b1,
                                                      const float* __restrict__ gamma,
                                                      const float* __restrict__ beta,
                                                      float* __restrict__ out) {
    extern __shared__ char smem[];
    uint32_t sbase = smem_u32(smem);
    float* xs = (float*)(smem + SMF_X);
    int n0 = blockIdx.x * 32;
    int t = threadIdx.x;
    int lane = t & 31, w = t >> 5;
    int rg = w >> 2, cg = w & 3;

    // prefetch chunk 0: A = cat rows n0..n0+31 k 0..127 (8KB, 256B rows);
    //                   B = W1 rows 0..127 (32KB)
#pragma unroll
    for (int i = 0; i < 2; ++i) {
        int u = t + i * 256;  // 0..511
        uint32_t row = (uint32_t)(u >> 4), j = (uint32_t)(u & 15);
        cp_async16(sbase + SMF_A + row * 256 + (swz(j, row) << 4),
                   g_attnb + (long long)(n0 + row) * (HH * DD) + j * 8);
    }
#pragma unroll
    for (int i = 0; i < 8; ++i) {
        int u = t + i * 256;  // 0..2047
        uint32_t brow = (uint32_t)(u >> 4), bj = (uint32_t)(u & 15);
        cp_async16(sbase + SMF_B + brow * 256 + (swz(bj, brow) << 4),
                   g_W1b + (long long)brow * DD + bj * 8);
    }
    cp_commit();

    int qr = lane >> 2, ko = (lane & 3) * 2;
    int lr16 = lane & 15, hi = lane >> 4;
    float c[4][4];
#pragma unroll
    for (int j = 0; j < 4; ++j) c[j][0] = c[j][1] = c[j][2] = c[j][3] = 0.f;

    for (int ch = 0; ch < 8; ++ch) {
        uint32_t abuf = sbase + SMF_A + (ch & 1) * 8192;
        uint32_t bbuf = sbase + SMF_B + (ch & 1) * 32768;
        if (ch + 1 < 8) {
            uint32_t abn = sbase + SMF_A + ((ch + 1) & 1) * 8192;
            uint32_t bbn = sbase + SMF_B + ((ch + 1) & 1) * 32768;
            int k0 = (ch + 1) * 128;
#pragma unroll
            for (int i = 0; i < 2; ++i) {
                int u = t + i * 256;
                uint32_t row = (uint32_t)(u >> 4), j = (uint32_t)(u & 15);
                cp_async16(abn + row * 256 + (swz(j, row) << 4),
                           g_attnb + (long long)(n0 + row) * (HH * DD) + k0 + j * 8);
            }
#pragma unroll
            for (int i = 0; i < 8; ++i) {
                int u = t + i * 256;
                uint32_t brow = (uint32_t)(u >> 4), bj = (uint32_t)(u & 15);
                cp_async16(bbn + brow * 256 + (swz(bj, brow) << 4),
                           g_W1b + (long long)(k0 + brow) * DD + bj * 8);
            }
        }
        cp_commit();
        cp_wait1();
        __syncthreads();

#pragma unroll
        for (int kk = 0; kk < 8; ++kk) {
            uint32_t arow = (uint32_t)(rg * 16 + lr16);
            uint32_t aj = (uint32_t)(kk * 2 + hi);
            uint32_t a0, a1, a2, a3;
            ldmatrix_x4(a0, a1, a2, a3, abuf + arow * 256 + (swz(aj, arow) << 4));
            uint32_t lrow = (uint32_t)(kk * 16 + lr16);
            uint32_t rowb = bbuf + lrow * 256;
#pragma unroll
            for (int jj = 0; jj < 2; ++jj) {
                uint32_t j2 = (uint32_t)(cg * 4 + jj * 2 + hi);
                uint32_t v0, v1, v2, v3;
                ldmatrix_x4_trans(v0, v1, v2, v3, rowb + (swz(j2, lrow) << 4));
                mma16816(c[jj * 2], a0, a1, a2, a3, v0, v1);
                mma16816(c[jj * 2 + 1], a0, a1, a2, a3, v2, v3);
            }
        }
        __syncthreads();
    }

    // x = elu(acc + b1) -> xs
    int row_lo = rg * 16 + qr, row_hi = row_lo + 8;
#pragma unroll
    for (int j = 0; j < 4; ++j) {
        int cb = cg * 32 + j * 8 + ko;
        float2 bv = *(const float2*)&b1[cb];
        xs[row_lo * 132 + cb] = eluf(c[j][0] + bv.x);
        xs[row_lo * 132 + cb + 1] = eluf(c[j][1] + bv.y);
        xs[row_hi * 132 + cb] = eluf(c[j][2] + bv.x);
        xs[row_hi * 132 + cb + 1] = eluf(c[j][3] + bv.y);
    }
    __syncthreads();

    // LN: warp w handles rows w*4..w*4+3
    int e2 = lane * 4;
    float4 gg = *(const float4*)&gamma[e2];
    float4 be = *(const float4*)&beta[e2];
#pragma unroll
    for (int rr = 0; rr < 4; ++rr) {
        int row = w * 4 + rr;
        int n = n0 + row;
        float4 xv = *(const float4*)&xs[row * 132 + e2];
        float4 nd = *(const float4*)&nodes[n * DD + e2];
        float4 y = make_float4(nd.x + xv.x, nd.y + xv.y, nd.z + xv.z, nd.w + xv.w);
        float s = y.x + y.y + y.z + y.w;
        float q = y.x * y.x + y.y * y.y + y.z * y.z + y.w * y.w;
#pragma unroll
        for (int o = 16; o; o >>= 1) {
            s += __shfl_xor_sync(0xffffffffu, s, o);
            q += __shfl_xor_sync(0xffffffffu, q, o);
        }
        float mu = s * (1.f / 128.f);
        float var = q * (1.f / 128.f) - mu * mu;
        float rsx = rsqrtf(var + EPSLN);
        float4 o4;
        o4.x = (y.x - mu) * rsx * gg.x + be.x;
        o4.y = (y.y - mu) * rsx * gg.y + be.y;
        o4.z = (y.z - mu) * rsx * gg.z + be.z;
        o4.w = (y.w - mu) * rsx * gg.w + be.w;
        *(float4*)&out[n * DD + e2] = o4;
    }
}

extern "C" void kernel_launch(void* const* d_in, const int* in_sizes, int n_in,
                              void* d_out, int out_size) {
    const float* nodes = (const float*)d_in[0];
    const int* adj = (const int*)d_in[1];
    const float* W = (const float*)d_in[2];
    const float* a1 = (const float*)d_in[3];
    const float* a2 = (const float*)d_in[4];
    const float* W1 = (const float*)d_in[5];
    const float* b1 = (const float*)d_in[6];
    const float* gamma = (const float*)d_in[7];
    const float* beta = (const float*)d_in[8];
    float* out = (float*)d_out;

    cudaFuncSetAttribute(k_attn, cudaFuncAttributeMaxDynamicSharedMemorySize, ATTN_SMEM);
    cudaFuncSetAttribute(k_wh_mma, cudaFuncAttributeMaxDynamicSharedMemorySize, WH_SMEM);
    cudaFuncSetAttribute(k_final_mma, cudaFuncAttributeMaxDynamicSharedMemorySize, FIN_SMEM);

    k_pre<<<NN + 256, 256>>>(nodes, W, W1, adj);
    k_wh_mma<<<dim3(NN / 128, HH), 256, WH_SMEM>>>(a1, a2);
    k_attn<<<dim3(HH, NN / 128), 256, ATTN_SMEM>>>();
    k_final_mma<<<NN / 32, 256, FIN_SMEM>>>(nodes, b1, gamma, beta, out);  // 4th -> profiled
}